// round 12
// baseline (speedup 1.0000x reference)
#include <cuda_runtime.h>
#include <cuda_fp16.h>
#include <math.h>
#include <stdint.h>

#define T_TOK 8192
#define H_DIM 1024
#define F_DIM 4096
#define NE    8
#define BM    256
#define BN    128
#define BK    64
#define DEPTH 3
#define NTHR  512

// ---------------- device scratch (static, no runtime allocation) ------------
__device__ __half g_h  [(size_t)(2 * T_TOK + BM) * F_DIM];  // gelu(x@w1+b1) fp16
__device__ float  g_h2 [(size_t)(2 * T_TOK + BM) * H_DIM];  // (h@w2+b2) fp32
__device__ __half g_w1h[(size_t)NE * H_DIM * F_DIM];        // fp16 w1
__device__ __half g_w2h[(size_t)NE * F_DIM * H_DIM];        // fp16 w2
__device__ __half g_xh [(size_t)T_TOK * H_DIM];             // fp16 x
__device__ int    g_tok[NE * T_TOK];
__device__ int    g_cnt[NE];
__device__ int    g_off[NE];
__device__ int    g_pE[2 * T_TOK];
__device__ int    g_pP[2 * T_TOK];
__device__ float  g_pW[2 * T_TOK];

// ---------------- helpers ----------------------------------------------------
__device__ __forceinline__ void mma16(float* d, const uint32_t* a, const uint32_t* b) {
    asm volatile(
        "mma.sync.aligned.m16n8k16.row.col.f32.f16.f16.f32 "
        "{%0,%1,%2,%3}, {%4,%5,%6,%7}, {%8,%9}, {%0,%1,%2,%3};"
        : "+f"(d[0]), "+f"(d[1]), "+f"(d[2]), "+f"(d[3])
        : "r"(a[0]), "r"(a[1]), "r"(a[2]), "r"(a[3]), "r"(b[0]), "r"(b[1]));
}
__device__ __forceinline__ void ldm4(uint32_t* r, uint32_t addr) {
    asm volatile("ldmatrix.sync.aligned.m8n8.x4.shared.b16 {%0,%1,%2,%3}, [%4];"
                 : "=r"(r[0]), "=r"(r[1]), "=r"(r[2]), "=r"(r[3]) : "r"(addr));
}
__device__ __forceinline__ void ldm4t(uint32_t* r, uint32_t addr) {
    asm volatile("ldmatrix.sync.aligned.m8n8.x4.trans.shared.b16 {%0,%1,%2,%3}, [%4];"
                 : "=r"(r[0]), "=r"(r[1]), "=r"(r[2]), "=r"(r[3]) : "r"(addr));
}
__device__ __forceinline__ uint32_t smem_u32(const void* p) {
    uint32_t a;
    asm("{ .reg .u64 t; cvta.to.shared.u64 t, %1; cvt.u32.u64 %0, t; }" : "=r"(a) : "l"(p));
    return a;
}
__device__ __forceinline__ void cp16(uint32_t dst, const void* src, bool pred) {
    int sz = pred ? 16 : 0;
    asm volatile("cp.async.cg.shared.global [%0], [%1], 16, %2;"
                 :: "r"(dst), "l"(src), "r"(sz) : "memory");
}
__device__ __forceinline__ void cp_commit() {
    asm volatile("cp.async.commit_group;" ::: "memory");
}
template <int N>
__device__ __forceinline__ void cp_wait() {
    asm volatile("cp.async.wait_group %0;" :: "n"(N) : "memory");
}
__device__ __forceinline__ float gelu_tanh(float v) {
    float u = 0.7978845608028654f * (v + 0.044715f * v * v * v);
    return 0.5f * v * (1.0f + tanhf(u));
}

// ---------------- fp32 -> fp16 convert pass ----------------------------------
__global__ __launch_bounds__(256) void to_half_kernel(const float* __restrict__ src,
                                                      __half* __restrict__ dst,
                                                      size_t n8) {
    size_t stride = (size_t)gridDim.x * blockDim.x;
    for (size_t i = blockIdx.x * (size_t)blockDim.x + threadIdx.x; i < n8; i += stride) {
        float4 v0 = ((const float4*)src)[2 * i];
        float4 v1 = ((const float4*)src)[2 * i + 1];
        __half2 h0 = __floats2half2_rn(v0.x, v0.y);
        __half2 h1 = __floats2half2_rn(v0.z, v0.w);
        __half2 h2 = __floats2half2_rn(v1.x, v1.y);
        __half2 h3 = __floats2half2_rn(v1.z, v1.w);
        uint4 o = {*(uint32_t*)&h0, *(uint32_t*)&h1, *(uint32_t*)&h2, *(uint32_t*)&h3};
        ((uint4*)dst)[i] = o;
    }
}

// ---------------- router ------------------------------------------------------
__global__ void zero_counts_kernel() {
    if (threadIdx.x < NE) g_cnt[threadIdx.x] = 0;
}
__global__ void scan_kernel() {
    if (threadIdx.x == 0) {
        int s = 0;
        for (int e = 0; e < NE; e++) { g_off[e] = s; s += g_cnt[e]; }
    }
}
__global__ __launch_bounds__(256) void router_kernel(const float* __restrict__ x,
                                                     const float* __restrict__ rw,
                                                     const float* __restrict__ rb) {
    int warp = threadIdx.x >> 5, lane = threadIdx.x & 31;
    int t = blockIdx.x * 8 + warp;
    if (t >= T_TOK) return;
    const float* xr = x + (size_t)t * H_DIM;
    float acc[NE];
#pragma unroll
    for (int e = 0; e < NE; e++) acc[e] = 0.f;
    for (int h = lane; h < H_DIM; h += 32) {
        float xv = xr[h];
        const float* wr = rw + h * NE;
#pragma unroll
        for (int e = 0; e < NE; e++) acc[e] += xv * wr[e];
    }
#pragma unroll
    for (int off = 16; off > 0; off >>= 1)
#pragma unroll
        for (int e = 0; e < NE; e++) acc[e] += __shfl_xor_sync(0xffffffffu, acc[e], off);
    if (lane == 0) {
#pragma unroll
        for (int e = 0; e < NE; e++) acc[e] += rb[e];
        int i1 = 0;
#pragma unroll
        for (int e = 1; e < NE; e++) if (acc[e] > acc[i1]) i1 = e;
        int i2 = -1;
#pragma unroll
        for (int e = 0; e < NE; e++) {
            if (e == i1) continue;
            if (i2 < 0 || acc[e] > acc[i2]) i2 = e;
        }
        float d   = acc[i2] - acc[i1];
        float w1p = 1.f / (1.f + expf(d));
        float w2p = 1.f - w1p;
        int p1 = atomicAdd(&g_cnt[i1], 1);
        g_tok[i1 * T_TOK + p1] = t;
        g_pE[2 * t] = i1; g_pP[2 * t] = p1; g_pW[2 * t] = w1p;
        int p2 = atomicAdd(&g_cnt[i2], 1);
        g_tok[i2 * T_TOK + p2] = t;
        g_pE[2 * t + 1] = i2; g_pP[2 * t + 1] = p2; g_pW[2 * t + 1] = w2p;
    }
}

// ---------------- fp16 mma.sync GEMM, BM=256, BK=64, cp.async ring -----------
// A smem: 256 rows x 64 half, row stride 144B -> ldmatrix conflict-free
// B smem: 64 k-rows x 128 half, row stride 272B -> ldm.trans conflict-free
#define A_STRIDE_B 144
#define B_STRIDE_B 272
#define A_BYTES   (BM * A_STRIDE_B)                 // 36864
#define B_BYTES   (BK * B_STRIDE_B)                 // 17408
#define STG_BYTES (A_BYTES + B_BYTES)               // 54272
#define SMEM_DYN  (DEPTH * STG_BYTES)               // 162816

template <bool PHASE2>
__global__ __launch_bounds__(NTHR, 1) void moe_mma(const __half* __restrict__ X,
                                                   const __half* __restrict__ W,
                                                   const float* __restrict__ Bias) {
    constexpr int KDIM   = PHASE2 ? F_DIM : H_DIM;
    constexpr int NDIM   = PHASE2 ? H_DIM : F_DIM;
    constexpr int STAGES = KDIM / BK;               // 16 / 64

    const int e    = blockIdx.z;
    const int cnt  = g_cnt[e];
    const int row0 = blockIdx.y * BM;
    if (row0 >= cnt) return;
    const int col0 = blockIdx.x * BN;
    const int off  = g_off[e];
    const __half* Wexp = W + (size_t)e * KDIM * NDIM;

    extern __shared__ uint32_t smu[];
    __shared__ int toks_s[BM];
    const int tid = threadIdx.x;
    if (!PHASE2 && tid < BM) {
        int pos = row0 + tid;
        toks_s[tid] = (pos < cnt) ? g_tok[e * T_TOK + pos] : -1;
    }
    __syncthreads();

    // A loader: row = tid>>1 (0..255), half-of-row = tid&1 -> 4x16B (32KB/stage)
    const int arow = tid >> 1, ah = tid & 1;
    const __half* aptr;
    bool avalid = true;
    if (PHASE2) {
        aptr = g_h + (size_t)(off + row0 + arow) * F_DIM;
    } else {
        int tk = toks_s[arow];
        avalid = tk >= 0;
        aptr = avalid ? (X + (size_t)tk * H_DIM) : X;
    }
    // B loader: rows bk0, bk0+32 (bk0 = tid>>4 in 0..31), chunk bc of 16 (16KB/stage)
    const int bk0 = tid >> 4, bc = tid & 15;
    const __half* bbase = Wexp + (size_t)bk0 * NDIM + col0 + bc * 8;

    const uint32_t smem_base = smem_u32(smu);
    const uint32_t a_off = (uint32_t)(arow * A_STRIDE_B + ah * 64);
    const uint32_t b_off = (uint32_t)(A_BYTES + bk0 * B_STRIDE_B + bc * 16);

    const int lane = tid & 31;
    const int g  = lane >> 2, t4 = lane & 3;
    const int wm = (tid >> 5) >> 2, wn = (tid >> 5) & 3;   // 4 x 4 warp grid

    // A fragment base (ldmatrix x4): row = lane&15, +16B for k-high 8
    uint32_t a_frag_off[4];
#pragma unroll
    for (int mt = 0; mt < 4; mt++)
        a_frag_off[mt] = (uint32_t)((wm * 64 + mt * 16 + (lane & 15)) * A_STRIDE_B +
                                    (lane >> 4) * 16);
    // B fragment base (ldmatrix x4 trans): krow = (lane&7) + ((lane>>3)&1)*8
    uint32_t b_frag_off[2];
#pragma unroll
    for (int ntp = 0; ntp < 2; ntp++)
        b_frag_off[ntp] = (uint32_t)(A_BYTES +
            ((lane & 7) + ((lane >> 3) & 1) * 8) * B_STRIDE_B +
            wn * 64 + ntp * 32 + (lane >> 4) * 16);

    float acc[4][4][4];
#pragma unroll
    for (int mt = 0; mt < 4; mt++)
#pragma unroll
        for (int nt = 0; nt < 4; nt++)
#pragma unroll
            for (int r = 0; r < 4; r++) acc[mt][nt][r] = 0.f;

    auto issue = [&](int t) {
        uint32_t sb = smem_base + (uint32_t)(t % DEPTH) * STG_BYTES;
        int k0 = t * BK;
#pragma unroll
        for (int j = 0; j < 4; j++)
            cp16(sb + a_off + (uint32_t)j * 16u, aptr + k0 + ah * 32 + j * 8, avalid);
#pragma unroll
        for (int i = 0; i < 2; i++)
            cp16(sb + b_off + (uint32_t)(i * 32 * B_STRIDE_B),
                 bbase + (size_t)(k0 + i * 32) * NDIM, true);
        cp_commit();
    };

#pragma unroll
    for (int t = 0; t < DEPTH - 1; t++) issue(t);

    for (int s = 0; s < STAGES; s++) {
        cp_wait<DEPTH - 2>();
        __syncthreads();
        if (s + DEPTH - 1 < STAGES) issue(s + DEPTH - 1);

        const uint32_t sslot = smem_base + (uint32_t)(s % DEPTH) * STG_BYTES;
#pragma unroll
        for (int ks = 0; ks < 4; ks++) {          // four k16 steps per BK=64
            uint32_t af[4][4], bf[2][4];
#pragma unroll
            for (int mt = 0; mt < 4; mt++)
                ldm4(af[mt], sslot + a_frag_off[mt] + (uint32_t)ks * 32u);
#pragma unroll
            for (int ntp = 0; ntp < 2; ntp++)
                ldm4t(bf[ntp], sslot + b_frag_off[ntp] + (uint32_t)(ks * 16 * B_STRIDE_B));
#pragma unroll
            for (int mt = 0; mt < 4; mt++)
#pragma unroll
                for (int ntp = 0; ntp < 2; ntp++) {
                    mma16(acc[mt][2 * ntp],     af[mt], &bf[ntp][0]);
                    mma16(acc[mt][2 * ntp + 1], af[mt], &bf[ntp][2]);
                }
        }
    }

    // ---- epilogue: c0/c1 at row g, c2/c3 at row g+8, cols 2*t4 (+1)
#pragma unroll
    for (int mt = 0; mt < 4; mt++) {
#pragma unroll
        for (int rr = 0; rr < 2; rr++) {
            int m   = wm * 64 + mt * 16 + g + rr * 8;
            int pos = row0 + m;
            if (pos >= cnt) continue;
#pragma unroll
            for (int nt = 0; nt < 4; nt++) {
                int n = col0 + wn * 32 + nt * 8 + 2 * t4;
                float v0 = acc[mt][nt][rr * 2 + 0] + Bias[e * NDIM + n];
                float v1 = acc[mt][nt][rr * 2 + 1] + Bias[e * NDIM + n + 1];
                if (!PHASE2) {
                    __half2 o = __floats2half2_rn(gelu_tanh(v0), gelu_tanh(v1));
                    *(uint32_t*)(g_h + (size_t)(off + pos) * F_DIM + n) =
                        *(uint32_t*)&o;
                } else {
                    float2 o = {v0, v1};
                    *(float2*)(g_h2 + (size_t)(off + pos) * H_DIM + n) = o;
                }
            }
        }
    }
}

// ---------------- combine: out[t] = w0*h2[slot0] + w1*h2[slot1] --------------
__global__ __launch_bounds__(256) void combine_kernel(float* __restrict__ out) {
    int t = blockIdx.x;
    int c = threadIdx.x * 4;
    int e0 = g_pE[2 * t],     e1 = g_pE[2 * t + 1];
    int s0 = g_off[e0] + g_pP[2 * t];
    int s1 = g_off[e1] + g_pP[2 * t + 1];
    float w0 = g_pW[2 * t], w1 = g_pW[2 * t + 1];
    float4 a = *(const float4*)(g_h2 + (size_t)s0 * H_DIM + c);
    float4 b = *(const float4*)(g_h2 + (size_t)s1 * H_DIM + c);
    float4 o;
    o.x = w0 * a.x + w1 * b.x;
    o.y = w0 * a.y + w1 * b.y;
    o.z = w0 * a.z + w1 * b.z;
    o.w = w0 * a.w + w1 * b.w;
    *(float4*)(out + (size_t)t * H_DIM + c) = o;
}

// ---------------- launch ------------------------------------------------------
extern "C" void kernel_launch(void* const* d_in, const int* in_sizes, int n_in,
                              void* d_out, int out_size) {
    const float* x  = (const float*)d_in[0];  // [B,S,H]
    const float* w1 = (const float*)d_in[1];  // [E,H,F]
    const float* b1 = (const float*)d_in[2];  // [E,F]
    const float* w2 = (const float*)d_in[3];  // [E,F,H]
    const float* b2 = (const float*)d_in[4];  // [E,H]
    const float* rw = (const float*)d_in[5];  // [H,E]
    const float* rb = (const float*)d_in[6];  // [E]
    float* out = (float*)d_out;

    cudaFuncSetAttribute(moe_mma<false>, cudaFuncAttributeMaxDynamicSharedMemorySize,
                         SMEM_DYN);
    cudaFuncSetAttribute(moe_mma<true>, cudaFuncAttributeMaxDynamicSharedMemorySize,
                         SMEM_DYN);

    static __half *p_w1h = nullptr, *p_w2h = nullptr, *p_xh = nullptr;
    if (!p_w1h) {
        cudaGetSymbolAddress((void**)&p_w1h, g_w1h);
        cudaGetSymbolAddress((void**)&p_w2h, g_w2h);
        cudaGetSymbolAddress((void**)&p_xh, g_xh);
    }

    dim3 block(NTHR);
    dim3 grid1(F_DIM / BN, T_TOK / BM, NE);  // 32 x 32 x 8
    dim3 grid2(H_DIM / BN, T_TOK / BM, NE);  //  8 x 32 x 8

    // order chosen so ncu -s 5 samples moe_mma<false>
    to_half_kernel<<<1024, 256>>>(x, p_xh, (size_t)T_TOK * H_DIM / 8);        // 0
    zero_counts_kernel<<<1, 32>>>();                                          // 1
    router_kernel<<<T_TOK / 8, 256>>>(x, rw, rb);                             // 2
    scan_kernel<<<1, 32>>>();                                                 // 3
    to_half_kernel<<<4096, 256>>>(w1, p_w1h, (size_t)NE * H_DIM * F_DIM / 8); // 4
    moe_mma<false><<<grid1, block, SMEM_DYN>>>(p_xh, p_w1h, b1);              // 5
    to_half_kernel<<<4096, 256>>>(w2, p_w2h, (size_t)NE * F_DIM * H_DIM / 8); // 6
    moe_mma<true ><<<grid2, block, SMEM_DYN>>>(nullptr, p_w2h, b2);           // 7
    combine_kernel<<<T_TOK, 256>>>(out);                                      // 8
}

// round 13
// speedup vs baseline: 1.0368x; 1.0368x over previous
#include <cuda_runtime.h>
#include <cuda_fp16.h>
#include <math.h>
#include <stdint.h>

#define T_TOK 8192
#define H_DIM 1024
#define F_DIM 4096
#define NE    8
#define BM    128
#define BN    128
#define BK    64
#define DEPTH 3

// ---------------- device scratch (static, no runtime allocation) ------------
__device__ __half g_h  [(size_t)(2 * T_TOK + BM) * F_DIM];  // gelu(x@w1+b1) fp16
__device__ float  g_h2 [(size_t)(2 * T_TOK + BM) * H_DIM];  // (h@w2+b2) fp32
__device__ __half g_w1h[(size_t)NE * H_DIM * F_DIM];        // fp16 w1
__device__ __half g_w2h[(size_t)NE * F_DIM * H_DIM];        // fp16 w2
__device__ __half g_xh [(size_t)T_TOK * H_DIM];             // fp16 x
__device__ int    g_tok[NE * T_TOK];
__device__ int    g_cnt[NE];
__device__ int    g_off[NE];
__device__ int    g_pE[2 * T_TOK];
__device__ int    g_pP[2 * T_TOK];
__device__ float  g_pW[2 * T_TOK];

// ---------------- helpers ----------------------------------------------------
__device__ __forceinline__ void mma16(float* d, const uint32_t* a, const uint32_t* b) {
    asm volatile(
        "mma.sync.aligned.m16n8k16.row.col.f32.f16.f16.f32 "
        "{%0,%1,%2,%3}, {%4,%5,%6,%7}, {%8,%9}, {%0,%1,%2,%3};"
        : "+f"(d[0]), "+f"(d[1]), "+f"(d[2]), "+f"(d[3])
        : "r"(a[0]), "r"(a[1]), "r"(a[2]), "r"(a[3]), "r"(b[0]), "r"(b[1]));
}
__device__ __forceinline__ void ldm4(uint32_t* r, uint32_t addr) {
    asm volatile("ldmatrix.sync.aligned.m8n8.x4.shared.b16 {%0,%1,%2,%3}, [%4];"
                 : "=r"(r[0]), "=r"(r[1]), "=r"(r[2]), "=r"(r[3]) : "r"(addr));
}
__device__ __forceinline__ void ldm4t(uint32_t* r, uint32_t addr) {
    asm volatile("ldmatrix.sync.aligned.m8n8.x4.trans.shared.b16 {%0,%1,%2,%3}, [%4];"
                 : "=r"(r[0]), "=r"(r[1]), "=r"(r[2]), "=r"(r[3]) : "r"(addr));
}
__device__ __forceinline__ uint32_t smem_u32(const void* p) {
    uint32_t a;
    asm("{ .reg .u64 t; cvta.to.shared.u64 t, %1; cvt.u32.u64 %0, t; }" : "=r"(a) : "l"(p));
    return a;
}
__device__ __forceinline__ void cp16(uint32_t dst, const void* src, bool pred) {
    int sz = pred ? 16 : 0;
    asm volatile("cp.async.cg.shared.global [%0], [%1], 16, %2;"
                 :: "r"(dst), "l"(src), "r"(sz) : "memory");
}
__device__ __forceinline__ void cp_commit() {
    asm volatile("cp.async.commit_group;" ::: "memory");
}
template <int N>
__device__ __forceinline__ void cp_wait() {
    asm volatile("cp.async.wait_group %0;" :: "n"(N) : "memory");
}
__device__ __forceinline__ float gelu_tanh(float v) {
    float u = 0.7978845608028654f * (v + 0.044715f * v * v * v);
    return 0.5f * v * (1.0f + tanhf(u));
}

// ---------------- fp32 -> fp16 convert pass ----------------------------------
__global__ __launch_bounds__(256) void to_half_kernel(const float* __restrict__ src,
                                                      __half* __restrict__ dst,
                                                      size_t n8) {
    size_t stride = (size_t)gridDim.x * blockDim.x;
    for (size_t i = blockIdx.x * (size_t)blockDim.x + threadIdx.x; i < n8; i += stride) {
        float4 v0 = ((const float4*)src)[2 * i];
        float4 v1 = ((const float4*)src)[2 * i + 1];
        __half2 h0 = __floats2half2_rn(v0.x, v0.y);
        __half2 h1 = __floats2half2_rn(v0.z, v0.w);
        __half2 h2 = __floats2half2_rn(v1.x, v1.y);
        __half2 h3 = __floats2half2_rn(v1.z, v1.w);
        uint4 o = {*(uint32_t*)&h0, *(uint32_t*)&h1, *(uint32_t*)&h2, *(uint32_t*)&h3};
        ((uint4*)dst)[i] = o;
    }
}

// ---------------- router (also emits fp16 x) ----------------------------------
__global__ void zero_counts_kernel() {
    if (threadIdx.x < NE) g_cnt[threadIdx.x] = 0;
}
__global__ void scan_kernel() {
    if (threadIdx.x == 0) {
        int s = 0;
        for (int e = 0; e < NE; e++) { g_off[e] = s; s += g_cnt[e]; }
    }
}
__global__ __launch_bounds__(256) void router_kernel(const float* __restrict__ x,
                                                     const float* __restrict__ rw,
                                                     const float* __restrict__ rb,
                                                     __half* __restrict__ xh) {
    int warp = threadIdx.x >> 5, lane = threadIdx.x & 31;
    int t = blockIdx.x * 8 + warp;
    if (t >= T_TOK) return;
    const float* xr = x + (size_t)t * H_DIM;
    float acc[NE];
#pragma unroll
    for (int e = 0; e < NE; e++) acc[e] = 0.f;
    for (int h = lane; h < H_DIM; h += 32) {
        float xv = xr[h];
        const float* wr = rw + h * NE;
#pragma unroll
        for (int e = 0; e < NE; e++) acc[e] += xv * wr[e];
    }
    // fp16 emission: coalesced half2 stores (rows are L1/L2 hot from loop above)
    {
        __half2* xo = (__half2*)(xh + (size_t)t * H_DIM);
        const float2* xi = (const float2*)xr;
        for (int p = lane; p < H_DIM / 2; p += 32) {
            float2 v = xi[p];
            xo[p] = __floats2half2_rn(v.x, v.y);
        }
    }
#pragma unroll
    for (int off = 16; off > 0; off >>= 1)
#pragma unroll
        for (int e = 0; e < NE; e++) acc[e] += __shfl_xor_sync(0xffffffffu, acc[e], off);
    if (lane == 0) {
#pragma unroll
        for (int e = 0; e < NE; e++) acc[e] += rb[e];
        int i1 = 0;
#pragma unroll
        for (int e = 1; e < NE; e++) if (acc[e] > acc[i1]) i1 = e;
        int i2 = -1;
#pragma unroll
        for (int e = 0; e < NE; e++) {
            if (e == i1) continue;
            if (i2 < 0 || acc[e] > acc[i2]) i2 = e;
        }
        float d   = acc[i2] - acc[i1];
        float w1p = 1.f / (1.f + expf(d));
        float w2p = 1.f - w1p;
        int p1 = atomicAdd(&g_cnt[i1], 1);
        g_tok[i1 * T_TOK + p1] = t;
        g_pE[2 * t] = i1; g_pP[2 * t] = p1; g_pW[2 * t] = w1p;
        int p2 = atomicAdd(&g_cnt[i2], 1);
        g_tok[i2 * T_TOK + p2] = t;
        g_pE[2 * t + 1] = i2; g_pP[2 * t + 1] = p2; g_pW[2 * t + 1] = w2p;
    }
}

// ---------------- fp16 mma.sync GEMM, BK=64, cp.async ring (round-11 proven) --
// A smem: 128 rows x 64 half, row stride 144B -> ldmatrix conflict-free
// B smem: 64 k-rows x 128 half, row stride 272B -> ldm.trans conflict-free
#define A_STRIDE_B 144
#define B_STRIDE_B 272
#define A_BYTES   (BM * A_STRIDE_B)                 // 18432
#define B_BYTES   (BK * B_STRIDE_B)                 // 17408
#define STG_BYTES (A_BYTES + B_BYTES)               // 35840
#define SMEM_DYN  (DEPTH * STG_BYTES)               // 107520

template <bool PHASE2>
__global__ __launch_bounds__(256, 2) void moe_mma(const __half* __restrict__ X,
                                                  const __half* __restrict__ W,
                                                  const float* __restrict__ Bias) {
    constexpr int KDIM   = PHASE2 ? F_DIM : H_DIM;
    constexpr int NDIM   = PHASE2 ? H_DIM : F_DIM;
    constexpr int STAGES = KDIM / BK;               // 16 / 64

    const int e    = blockIdx.z;
    const int cnt  = g_cnt[e];
    const int row0 = blockIdx.y * BM;
    if (row0 >= cnt) return;
    const int col0 = blockIdx.x * BN;
    const int off  = g_off[e];
    const __half* Wexp = W + (size_t)e * KDIM * NDIM;

    extern __shared__ uint32_t smu[];
    __shared__ int toks_s[BM];
    const int tid = threadIdx.x;
    if (!PHASE2 && tid < BM) {
        int pos = row0 + tid;
        toks_s[tid] = (pos < cnt) ? g_tok[e * T_TOK + pos] : -1;
    }
    __syncthreads();

    // A loader: row = tid&127, half-of-row = tid>>7 -> 4x16B each (16KB/stage)
    const int arow = tid & 127, ah = tid >> 7;
    const __half* aptr;
    bool avalid = true;
    if (PHASE2) {
        aptr = g_h + (size_t)(off + row0 + arow) * F_DIM;
    } else {
        int tk = toks_s[arow];
        avalid = tk >= 0;
        aptr = avalid ? (X + (size_t)tk * H_DIM) : X;
    }
    // B loader: rows bk0+16i (i=0..3), chunk bc of 16 -> 4x16B each (16KB/stage)
    const int bk0 = tid >> 4, bc = tid & 15;
    const __half* bbase = Wexp + (size_t)bk0 * NDIM + col0 + bc * 8;

    const uint32_t smem_base = smem_u32(smu);
    const uint32_t a_off = (uint32_t)(arow * A_STRIDE_B + ah * 64);
    const uint32_t b_off = (uint32_t)(A_BYTES + bk0 * B_STRIDE_B + bc * 16);

    const int lane = tid & 31;
    const int g  = lane >> 2, t4 = lane & 3;
    const int wm = (tid >> 5) >> 2, wn = (tid >> 5) & 3;

    // A fragment base (ldmatrix x4): row = lane&15, +16B for k-high 8
    uint32_t a_frag_off[4];
#pragma unroll
    for (int mt = 0; mt < 4; mt++)
        a_frag_off[mt] = (uint32_t)((wm * 64 + mt * 16 + (lane & 15)) * A_STRIDE_B +
                                    (lane >> 4) * 16);
    // B fragment base (ldmatrix x4 trans): krow = (lane&7) + ((lane>>3)&1)*8
    uint32_t b_frag_off[2];
#pragma unroll
    for (int ntp = 0; ntp < 2; ntp++)
        b_frag_off[ntp] = (uint32_t)(A_BYTES +
            ((lane & 7) + ((lane >> 3) & 1) * 8) * B_STRIDE_B +
            wn * 64 + ntp * 32 + (lane >> 4) * 16);

    float acc[4][4][4];
#pragma unroll
    for (int mt = 0; mt < 4; mt++)
#pragma unroll
        for (int nt = 0; nt < 4; nt++)
#pragma unroll
            for (int r = 0; r < 4; r++) acc[mt][nt][r] = 0.f;

    auto issue = [&](int t) {
        uint32_t sb = smem_base + (uint32_t)(t % DEPTH) * STG_BYTES;
        int k0 = t * BK;
#pragma unroll
        for (int j = 0; j < 4; j++)
            cp16(sb + a_off + (uint32_t)j * 16u, aptr + k0 + ah * 32 + j * 8, avalid);
#pragma unroll
        for (int i = 0; i < 4; i++)
            cp16(sb + b_off + (uint32_t)(i * 16 * B_STRIDE_B),
                 bbase + (size_t)(k0 + i * 16) * NDIM, true);
        cp_commit();
    };

#pragma unroll
    for (int t = 0; t < DEPTH - 1; t++) issue(t);

    for (int s = 0; s < STAGES; s++) {
        cp_wait<DEPTH - 2>();
        __syncthreads();
        if (s + DEPTH - 1 < STAGES) issue(s + DEPTH - 1);

        const uint32_t sslot = smem_base + (uint32_t)(s % DEPTH) * STG_BYTES;
#pragma unroll
        for (int ks = 0; ks < 4; ks++) {          // four k16 steps per BK=64
            uint32_t af[4][4], bf[2][4];
#pragma unroll
            for (int mt = 0; mt < 4; mt++)
                ldm4(af[mt], sslot + a_frag_off[mt] + (uint32_t)ks * 32u);
#pragma unroll
            for (int ntp = 0; ntp < 2; ntp++)
                ldm4t(bf[ntp], sslot + b_frag_off[ntp] + (uint32_t)(ks * 16 * B_STRIDE_B));
#pragma unroll
            for (int mt = 0; mt < 4; mt++)
#pragma unroll
                for (int ntp = 0; ntp < 2; ntp++) {
                    mma16(acc[mt][2 * ntp],     af[mt], &bf[ntp][0]);
                    mma16(acc[mt][2 * ntp + 1], af[mt], &bf[ntp][2]);
                }
        }
    }

    // ---- epilogue: c0/c1 at row g, c2/c3 at row g+8, cols 2*t4 (+1)
#pragma unroll
    for (int mt = 0; mt < 4; mt++) {
#pragma unroll
        for (int rr = 0; rr < 2; rr++) {
            int m   = wm * 64 + mt * 16 + g + rr * 8;
            int pos = row0 + m;
            if (pos >= cnt) continue;
#pragma unroll
            for (int nt = 0; nt < 4; nt++) {
                int n = col0 + wn * 32 + nt * 8 + 2 * t4;
                float v0 = acc[mt][nt][rr * 2 + 0] + Bias[e * NDIM + n];
                float v1 = acc[mt][nt][rr * 2 + 1] + Bias[e * NDIM + n + 1];
                if (!PHASE2) {
                    __half2 o = __floats2half2_rn(gelu_tanh(v0), gelu_tanh(v1));
                    *(uint32_t*)(g_h + (size_t)(off + pos) * F_DIM + n) =
                        *(uint32_t*)&o;
                } else {
                    float2 o = {v0, v1};
                    *(float2*)(g_h2 + (size_t)(off + pos) * H_DIM + n) = o;
                }
            }
        }
    }
}

// ---------------- combine: out[t] = w0*h2[slot0] + w1*h2[slot1] --------------
__global__ __launch_bounds__(256) void combine_kernel(float* __restrict__ out) {
    int t = blockIdx.x;
    int c = threadIdx.x * 4;
    int e0 = g_pE[2 * t],     e1 = g_pE[2 * t + 1];
    int s0 = g_off[e0] + g_pP[2 * t];
    int s1 = g_off[e1] + g_pP[2 * t + 1];
    float w0 = g_pW[2 * t], w1 = g_pW[2 * t + 1];
    float4 a = *(const float4*)(g_h2 + (size_t)s0 * H_DIM + c);
    float4 b = *(const float4*)(g_h2 + (size_t)s1 * H_DIM + c);
    float4 o;
    o.x = w0 * a.x + w1 * b.x;
    o.y = w0 * a.y + w1 * b.y;
    o.z = w0 * a.z + w1 * b.z;
    o.w = w0 * a.w + w1 * b.w;
    *(float4*)(out + (size_t)t * H_DIM + c) = o;
}

// ---------------- launch ------------------------------------------------------
extern "C" void kernel_launch(void* const* d_in, const int* in_sizes, int n_in,
                              void* d_out, int out_size) {
    const float* x  = (const float*)d_in[0];  // [B,S,H]
    const float* w1 = (const float*)d_in[1];  // [E,H,F]
    const float* b1 = (const float*)d_in[2];  // [E,F]
    const float* w2 = (const float*)d_in[3];  // [E,F,H]
    const float* b2 = (const float*)d_in[4];  // [E,H]
    const float* rw = (const float*)d_in[5];  // [H,E]
    const float* rb = (const float*)d_in[6];  // [E]
    float* out = (float*)d_out;

    cudaFuncSetAttribute(moe_mma<false>, cudaFuncAttributeMaxDynamicSharedMemorySize,
                         SMEM_DYN);
    cudaFuncSetAttribute(moe_mma<true>, cudaFuncAttributeMaxDynamicSharedMemorySize,
                         SMEM_DYN);

    static __half *p_w1h = nullptr, *p_w2h = nullptr, *p_xh = nullptr;
    if (!p_w1h) {
        cudaGetSymbolAddress((void**)&p_w1h, g_w1h);
        cudaGetSymbolAddress((void**)&p_w2h, g_w2h);
        cudaGetSymbolAddress((void**)&p_xh, g_xh);
    }

    dim3 block(256);
    dim3 grid1(F_DIM / BN, T_TOK / BM, NE);  // 32 x 64 x 8
    dim3 grid2(H_DIM / BN, T_TOK / BM, NE);  //  8 x 64 x 8

    zero_counts_kernel<<<1, 32>>>();                                          // 0
    router_kernel<<<T_TOK / 8, 256>>>(x, rw, rb, p_xh);                       // 1 (emits fp16 x)
    scan_kernel<<<1, 32>>>();                                                 // 2
    to_half_kernel<<<4096, 256>>>(w1, p_w1h, (size_t)NE * H_DIM * F_DIM / 8); // 3
    to_half_kernel<<<4096, 256>>>(w2, p_w2h, (size_t)NE * F_DIM * H_DIM / 8); // 4
    moe_mma<false><<<grid1, block, SMEM_DYN>>>(p_xh, p_w1h, b1);              // 5
    moe_mma<true ><<<grid2, block, SMEM_DYN>>>(nullptr, p_w2h, b2);           // 6
    combine_kernel<<<T_TOK, 256>>>(out);                                      // 7
}

// round 14
// speedup vs baseline: 1.0415x; 1.0046x over previous
#include <cuda_runtime.h>
#include <cuda_fp16.h>
#include <math.h>
#include <stdint.h>

#define T_TOK 8192
#define H_DIM 1024
#define F_DIM 4096
#define NE    8
#define BM    128
#define BN    128
#define BK    64
#define DEPTH 3

// ---------------- device scratch (static, no runtime allocation) ------------
__device__ __half g_h  [(size_t)(2 * T_TOK + BM) * F_DIM];  // gelu(x@w1+b1) fp16
__device__ __half g_w1h[(size_t)NE * H_DIM * F_DIM];        // fp16 w1
__device__ __half g_w2h[(size_t)NE * F_DIM * H_DIM];        // fp16 w2
__device__ __half g_xh [(size_t)T_TOK * H_DIM];             // fp16 x
__device__ int    g_tok[NE * T_TOK];
__device__ float  g_wt [NE * T_TOK];                        // per-(expert,pos) weight
__device__ int    g_cnt[NE];
__device__ int    g_off[NE];

// ---------------- helpers ----------------------------------------------------
__device__ __forceinline__ void mma16(float* d, const uint32_t* a, const uint32_t* b) {
    asm volatile(
        "mma.sync.aligned.m16n8k16.row.col.f32.f16.f16.f32 "
        "{%0,%1,%2,%3}, {%4,%5,%6,%7}, {%8,%9}, {%0,%1,%2,%3};"
        : "+f"(d[0]), "+f"(d[1]), "+f"(d[2]), "+f"(d[3])
        : "r"(a[0]), "r"(a[1]), "r"(a[2]), "r"(a[3]), "r"(b[0]), "r"(b[1]));
}
__device__ __forceinline__ void ldm4(uint32_t* r, uint32_t addr) {
    asm volatile("ldmatrix.sync.aligned.m8n8.x4.shared.b16 {%0,%1,%2,%3}, [%4];"
                 : "=r"(r[0]), "=r"(r[1]), "=r"(r[2]), "=r"(r[3]) : "r"(addr));
}
__device__ __forceinline__ void ldm4t(uint32_t* r, uint32_t addr) {
    asm volatile("ldmatrix.sync.aligned.m8n8.x4.trans.shared.b16 {%0,%1,%2,%3}, [%4];"
                 : "=r"(r[0]), "=r"(r[1]), "=r"(r[2]), "=r"(r[3]) : "r"(addr));
}
__device__ __forceinline__ uint32_t smem_u32(const void* p) {
    uint32_t a;
    asm("{ .reg .u64 t; cvta.to.shared.u64 t, %1; cvt.u32.u64 %0, t; }" : "=r"(a) : "l"(p));
    return a;
}
__device__ __forceinline__ void cp16(uint32_t dst, const void* src, bool pred) {
    int sz = pred ? 16 : 0;
    asm volatile("cp.async.cg.shared.global [%0], [%1], 16, %2;"
                 :: "r"(dst), "l"(src), "r"(sz) : "memory");
}
__device__ __forceinline__ void cp_commit() {
    asm volatile("cp.async.commit_group;" ::: "memory");
}
template <int N>
__device__ __forceinline__ void cp_wait() {
    asm volatile("cp.async.wait_group %0;" :: "n"(N) : "memory");
}
__device__ __forceinline__ float gelu_tanh(float v) {
    float u = 0.7978845608028654f * (v + 0.044715f * v * v * v);
    return 0.5f * v * (1.0f + tanhf(u));
}

// ---------------- fp32 -> fp16 convert pass ----------------------------------
__global__ __launch_bounds__(256) void to_half_kernel(const float* __restrict__ src,
                                                      __half* __restrict__ dst,
                                                      size_t n8) {
    size_t stride = (size_t)gridDim.x * blockDim.x;
    for (size_t i = blockIdx.x * (size_t)blockDim.x + threadIdx.x; i < n8; i += stride) {
        float4 v0 = ((const float4*)src)[2 * i];
        float4 v1 = ((const float4*)src)[2 * i + 1];
        __half2 h0 = __floats2half2_rn(v0.x, v0.y);
        __half2 h1 = __floats2half2_rn(v0.z, v0.w);
        __half2 h2 = __floats2half2_rn(v1.x, v1.y);
        __half2 h3 = __floats2half2_rn(v1.z, v1.w);
        uint4 o = {*(uint32_t*)&h0, *(uint32_t*)&h1, *(uint32_t*)&h2, *(uint32_t*)&h3};
        ((uint4*)dst)[i] = o;
    }
}

// ---------------- router (also emits fp16 x) ----------------------------------
__global__ void zero_counts_kernel() {
    if (threadIdx.x < NE) g_cnt[threadIdx.x] = 0;
}
__global__ void scan_kernel() {
    if (threadIdx.x == 0) {
        int s = 0;
        for (int e = 0; e < NE; e++) { g_off[e] = s; s += g_cnt[e]; }
    }
}
__global__ __launch_bounds__(256) void router_kernel(const float* __restrict__ x,
                                                     const float* __restrict__ rw,
                                                     const float* __restrict__ rb,
                                                     __half* __restrict__ xh) {
    int warp = threadIdx.x >> 5, lane = threadIdx.x & 31;
    int t = blockIdx.x * 8 + warp;
    if (t >= T_TOK) return;
    const float* xr = x + (size_t)t * H_DIM;
    float acc[NE];
#pragma unroll
    for (int e = 0; e < NE; e++) acc[e] = 0.f;
    for (int h = lane; h < H_DIM; h += 32) {
        float xv = xr[h];
        const float* wr = rw + h * NE;
#pragma unroll
        for (int e = 0; e < NE; e++) acc[e] += xv * wr[e];
    }
    // fp16 emission: coalesced half2 stores (rows are hot in L1/L2)
    {
        __half2* xo = (__half2*)(xh + (size_t)t * H_DIM);
        const float2* xi = (const float2*)xr;
        for (int p = lane; p < H_DIM / 2; p += 32) {
            float2 v = xi[p];
            xo[p] = __floats2half2_rn(v.x, v.y);
        }
    }
#pragma unroll
    for (int off = 16; off > 0; off >>= 1)
#pragma unroll
        for (int e = 0; e < NE; e++) acc[e] += __shfl_xor_sync(0xffffffffu, acc[e], off);
    if (lane == 0) {
#pragma unroll
        for (int e = 0; e < NE; e++) acc[e] += rb[e];
        int i1 = 0;
#pragma unroll
        for (int e = 1; e < NE; e++) if (acc[e] > acc[i1]) i1 = e;
        int i2 = -1;
#pragma unroll
        for (int e = 0; e < NE; e++) {
            if (e == i1) continue;
            if (i2 < 0 || acc[e] > acc[i2]) i2 = e;
        }
        float d   = acc[i2] - acc[i1];
        float w1p = 1.f / (1.f + expf(d));
        float w2p = 1.f - w1p;
        int p1 = atomicAdd(&g_cnt[i1], 1);
        g_tok[i1 * T_TOK + p1] = t;
        g_wt [i1 * T_TOK + p1] = w1p;
        int p2 = atomicAdd(&g_cnt[i2], 1);
        g_tok[i2 * T_TOK + p2] = t;
        g_wt [i2 * T_TOK + p2] = w2p;
    }
}

// ---------------- fp16 mma.sync GEMM, BK=64, cp.async ring -------------------
// A smem: 128 rows x 64 half, row stride 144B -> ldmatrix conflict-free
// B smem: 64 k-rows x 128 half, row stride 272B -> ldm.trans conflict-free
#define A_STRIDE_B 144
#define B_STRIDE_B 272
#define A_BYTES   (BM * A_STRIDE_B)                 // 18432
#define B_BYTES   (BK * B_STRIDE_B)                 // 17408
#define STG_BYTES (A_BYTES + B_BYTES)               // 35840
#define SMEM_DYN  (DEPTH * STG_BYTES)               // 107520

// PHASE2=false: g_h[slot] = gelu(x@w1+b1)
// PHASE2=true : out[tok]  += wt * (g_h[slot]@w2 + b2)   (atomic, 2 adds/element)
template <bool PHASE2>
__global__ __launch_bounds__(256, 2) void moe_mma(const __half* __restrict__ X,
                                                  const __half* __restrict__ W,
                                                  const float* __restrict__ Bias,
                                                  float* __restrict__ Out) {
    constexpr int KDIM   = PHASE2 ? F_DIM : H_DIM;
    constexpr int NDIM   = PHASE2 ? H_DIM : F_DIM;
    constexpr int STAGES = KDIM / BK;               // 16 / 64

    const int e    = blockIdx.z;
    const int cnt  = g_cnt[e];
    const int row0 = blockIdx.y * BM;
    if (row0 >= cnt) return;
    const int col0 = blockIdx.x * BN;
    const int off  = g_off[e];
    const __half* Wexp = W + (size_t)e * KDIM * NDIM;

    extern __shared__ uint32_t smu[];
    __shared__ int   toks_s[BM];
    __shared__ float wts_s[BM];
    const int tid = threadIdx.x;
    if (tid < BM) {
        int pos = row0 + tid;
        toks_s[tid] = (pos < cnt) ? g_tok[e * T_TOK + pos] : -1;
        if (PHASE2) wts_s[tid] = (pos < cnt) ? g_wt[e * T_TOK + pos] : 0.f;
    }
    __syncthreads();

    // A loader: row = tid&127, half-of-row = tid>>7 -> 4x16B each (16KB/stage)
    const int arow = tid & 127, ah = tid >> 7;
    const __half* aptr;
    bool avalid = true;
    if (PHASE2) {
        aptr = g_h + (size_t)(off + row0 + arow) * F_DIM;
    } else {
        int tk = toks_s[arow];
        avalid = tk >= 0;
        aptr = avalid ? (X + (size_t)tk * H_DIM) : X;
    }
    // B loader: rows bk0+16i (i=0..3), chunk bc of 16 -> 4x16B each (16KB/stage)
    const int bk0 = tid >> 4, bc = tid & 15;
    const __half* bbase = Wexp + (size_t)bk0 * NDIM + col0 + bc * 8;

    const uint32_t smem_base = smem_u32(smu);
    const uint32_t a_off = (uint32_t)(arow * A_STRIDE_B + ah * 64);
    const uint32_t b_off = (uint32_t)(A_BYTES + bk0 * B_STRIDE_B + bc * 16);

    const int lane = tid & 31;
    const int g  = lane >> 2, t4 = lane & 3;
    const int wm = (tid >> 5) >> 2, wn = (tid >> 5) & 3;

    // A fragment base (ldmatrix x4): row = lane&15, +16B for k-high 8
    uint32_t a_frag_off[4];
#pragma unroll
    for (int mt = 0; mt < 4; mt++)
        a_frag_off[mt] = (uint32_t)((wm * 64 + mt * 16 + (lane & 15)) * A_STRIDE_B +
                                    (lane >> 4) * 16);
    // B fragment base (ldmatrix x4 trans): krow = (lane&7) + ((lane>>3)&1)*8
    uint32_t b_frag_off[2];
#pragma unroll
    for (int ntp = 0; ntp < 2; ntp++)
        b_frag_off[ntp] = (uint32_t)(A_BYTES +
            ((lane & 7) + ((lane >> 3) & 1) * 8) * B_STRIDE_B +
            wn * 64 + ntp * 32 + (lane >> 4) * 16);

    float acc[4][4][4];
#pragma unroll
    for (int mt = 0; mt < 4; mt++)
#pragma unroll
        for (int nt = 0; nt < 4; nt++)
#pragma unroll
            for (int r = 0; r < 4; r++) acc[mt][nt][r] = 0.f;

    auto issue = [&](int t) {
        uint32_t sb = smem_base + (uint32_t)(t % DEPTH) * STG_BYTES;
        int k0 = t * BK;
#pragma unroll
        for (int j = 0; j < 4; j++)
            cp16(sb + a_off + (uint32_t)j * 16u, aptr + k0 + ah * 32 + j * 8, avalid);
#pragma unroll
        for (int i = 0; i < 4; i++)
            cp16(sb + b_off + (uint32_t)(i * 16 * B_STRIDE_B),
                 bbase + (size_t)(k0 + i * 16) * NDIM, true);
        cp_commit();
    };

#pragma unroll
    for (int t = 0; t < DEPTH - 1; t++) issue(t);

    for (int s = 0; s < STAGES; s++) {
        cp_wait<DEPTH - 2>();
        __syncthreads();
        if (s + DEPTH - 1 < STAGES) issue(s + DEPTH - 1);

        const uint32_t sslot = smem_base + (uint32_t)(s % DEPTH) * STG_BYTES;
#pragma unroll
        for (int ks = 0; ks < 4; ks++) {          // four k16 steps per BK=64
            uint32_t af[4][4], bf[2][4];
#pragma unroll
            for (int mt = 0; mt < 4; mt++)
                ldm4(af[mt], sslot + a_frag_off[mt] + (uint32_t)ks * 32u);
#pragma unroll
            for (int ntp = 0; ntp < 2; ntp++)
                ldm4t(bf[ntp], sslot + b_frag_off[ntp] + (uint32_t)(ks * 16 * B_STRIDE_B));
#pragma unroll
            for (int mt = 0; mt < 4; mt++)
#pragma unroll
                for (int ntp = 0; ntp < 2; ntp++) {
                    mma16(acc[mt][2 * ntp],     af[mt], &bf[ntp][0]);
                    mma16(acc[mt][2 * ntp + 1], af[mt], &bf[ntp][2]);
                }
        }
    }

    // ---- epilogue: c0/c1 at row g, c2/c3 at row g+8, cols 2*t4 (+1)
#pragma unroll
    for (int mt = 0; mt < 4; mt++) {
#pragma unroll
        for (int rr = 0; rr < 2; rr++) {
            int m   = wm * 64 + mt * 16 + g + rr * 8;
            int pos = row0 + m;
            if (pos >= cnt) continue;
#pragma unroll
            for (int nt = 0; nt < 4; nt++) {
                int n = col0 + wn * 32 + nt * 8 + 2 * t4;
                float v0 = acc[mt][nt][rr * 2 + 0] + Bias[e * NDIM + n];
                float v1 = acc[mt][nt][rr * 2 + 1] + Bias[e * NDIM + n + 1];
                if (!PHASE2) {
                    __half2 o = __floats2half2_rn(gelu_tanh(v0), gelu_tanh(v1));
                    *(uint32_t*)(g_h + (size_t)(off + pos) * F_DIM + n) =
                        *(uint32_t*)&o;
                } else {
                    int   tk = toks_s[m];
                    float wv = wts_s[m];
                    float* orow = Out + (size_t)tk * H_DIM + n;
                    atomicAdd(&orow[0], wv * v0);
                    atomicAdd(&orow[1], wv * v1);
                }
            }
        }
    }
}

// ---------------- launch ------------------------------------------------------
extern "C" void kernel_launch(void* const* d_in, const int* in_sizes, int n_in,
                              void* d_out, int out_size) {
    const float* x  = (const float*)d_in[0];  // [B,S,H]
    const float* w1 = (const float*)d_in[1];  // [E,H,F]
    const float* b1 = (const float*)d_in[2];  // [E,F]
    const float* w2 = (const float*)d_in[3];  // [E,F,H]
    const float* b2 = (const float*)d_in[4];  // [E,H]
    const float* rw = (const float*)d_in[5];  // [H,E]
    const float* rb = (const float*)d_in[6];  // [E]
    float* out = (float*)d_out;

    cudaFuncSetAttribute(moe_mma<false>, cudaFuncAttributeMaxDynamicSharedMemorySize,
                         SMEM_DYN);
    cudaFuncSetAttribute(moe_mma<true>, cudaFuncAttributeMaxDynamicSharedMemorySize,
                         SMEM_DYN);

    static __half *p_w1h = nullptr, *p_w2h = nullptr, *p_xh = nullptr;
    static cudaStream_t s2;
    static cudaEvent_t evStart, ev1, ev2;
    if (!p_w1h) {
        cudaGetSymbolAddress((void**)&p_w1h, g_w1h);
        cudaGetSymbolAddress((void**)&p_w2h, g_w2h);
        cudaGetSymbolAddress((void**)&p_xh, g_xh);
        cudaStreamCreateWithFlags(&s2, cudaStreamNonBlocking);
        cudaEventCreateWithFlags(&evStart, cudaEventDisableTiming);
        cudaEventCreateWithFlags(&ev1, cudaEventDisableTiming);
        cudaEventCreateWithFlags(&ev2, cudaEventDisableTiming);
    }

    dim3 block(256);
    dim3 grid1(F_DIM / BN, T_TOK / BM, NE);  // 32 x 64 x 8
    dim3 grid2(H_DIM / BN, T_TOK / BM, NE);  //  8 x 64 x 8

    // fork: weight converts on s2, overlapped with router (w1) and moe1 (w2)
    cudaEventRecord(evStart, 0);
    cudaStreamWaitEvent(s2, evStart, 0);
    to_half_kernel<<<4096, 256, 0, s2>>>(w1, p_w1h, (size_t)NE * H_DIM * F_DIM / 8);
    cudaEventRecord(ev1, s2);
    to_half_kernel<<<4096, 256, 0, s2>>>(w2, p_w2h, (size_t)NE * F_DIM * H_DIM / 8);
    cudaEventRecord(ev2, s2);

    cudaMemsetAsync(out, 0, (size_t)T_TOK * H_DIM * sizeof(float), 0);
    zero_counts_kernel<<<1, 32>>>();
    router_kernel<<<T_TOK / 8, 256>>>(x, rw, rb, p_xh);
    scan_kernel<<<1, 32>>>();

    cudaStreamWaitEvent(0, ev1, 0);
    moe_mma<false><<<grid1, block, SMEM_DYN>>>(p_xh, p_w1h, b1, nullptr);
    cudaStreamWaitEvent(0, ev2, 0);
    moe_mma<true ><<<grid2, block, SMEM_DYN>>>(nullptr, p_w2h, b2, out);
}

// round 15
// speedup vs baseline: 1.0726x; 1.0298x over previous
#include <cuda_runtime.h>
#include <cuda_fp16.h>
#include <math.h>
#include <stdint.h>

#define T_TOK 8192
#define H_DIM 1024
#define F_DIM 4096
#define NE    8
#define BM    128
#define BN    128
#define BK    64
#define DEPTH 3

// ---------------- device scratch (static, no runtime allocation) ------------
__device__ __half g_h  [(size_t)(2 * T_TOK + BM) * F_DIM];  // gelu(x@w1+b1) fp16
__device__ float  g_h2 [(size_t)(2 * T_TOK + BM) * H_DIM];  // (h@w2+b2) fp32
__device__ __half g_w1h[(size_t)NE * H_DIM * F_DIM];        // fp16 w1
__device__ __half g_w2h[(size_t)NE * F_DIM * H_DIM];        // fp16 w2
__device__ __half g_xh [(size_t)T_TOK * H_DIM];             // fp16 x
__device__ float  g_rwT[NE * H_DIM];                        // transposed router w
__device__ int    g_tok[NE * T_TOK];
__device__ int    g_cnt[NE];
__device__ int    g_off[NE];
__device__ int    g_pE[2 * T_TOK];
__device__ int    g_pP[2 * T_TOK];
__device__ float  g_pW[2 * T_TOK];

// ---------------- helpers ----------------------------------------------------
__device__ __forceinline__ void mma16(float* d, const uint32_t* a, const uint32_t* b) {
    asm volatile(
        "mma.sync.aligned.m16n8k16.row.col.f32.f16.f16.f32 "
        "{%0,%1,%2,%3}, {%4,%5,%6,%7}, {%8,%9}, {%0,%1,%2,%3};"
        : "+f"(d[0]), "+f"(d[1]), "+f"(d[2]), "+f"(d[3])
        : "r"(a[0]), "r"(a[1]), "r"(a[2]), "r"(a[3]), "r"(b[0]), "r"(b[1]));
}
__device__ __forceinline__ void ldm4(uint32_t* r, uint32_t addr) {
    asm volatile("ldmatrix.sync.aligned.m8n8.x4.shared.b16 {%0,%1,%2,%3}, [%4];"
                 : "=r"(r[0]), "=r"(r[1]), "=r"(r[2]), "=r"(r[3]) : "r"(addr));
}
__device__ __forceinline__ void ldm4t(uint32_t* r, uint32_t addr) {
    asm volatile("ldmatrix.sync.aligned.m8n8.x4.trans.shared.b16 {%0,%1,%2,%3}, [%4];"
                 : "=r"(r[0]), "=r"(r[1]), "=r"(r[2]), "=r"(r[3]) : "r"(addr));
}
__device__ __forceinline__ uint32_t smem_u32(const void* p) {
    uint32_t a;
    asm("{ .reg .u64 t; cvta.to.shared.u64 t, %1; cvt.u32.u64 %0, t; }" : "=r"(a) : "l"(p));
    return a;
}
__device__ __forceinline__ void cp16(uint32_t dst, const void* src, bool pred) {
    int sz = pred ? 16 : 0;
    asm volatile("cp.async.cg.shared.global [%0], [%1], 16, %2;"
                 :: "r"(dst), "l"(src), "r"(sz) : "memory");
}
__device__ __forceinline__ void cp_commit() {
    asm volatile("cp.async.commit_group;" ::: "memory");
}
template <int N>
__device__ __forceinline__ void cp_wait() {
    asm volatile("cp.async.wait_group %0;" :: "n"(N) : "memory");
}
__device__ __forceinline__ float gelu_tanh(float v) {
    float u = 0.7978845608028654f * (v + 0.044715f * v * v * v);
    return 0.5f * v * (1.0f + tanhf(u));
}

// ---------------- fp32 -> fp16 convert pass ----------------------------------
__global__ __launch_bounds__(256) void to_half_kernel(const float* __restrict__ src,
                                                      __half* __restrict__ dst,
                                                      size_t n8) {
    size_t stride = (size_t)gridDim.x * blockDim.x;
    for (size_t i = blockIdx.x * (size_t)blockDim.x + threadIdx.x; i < n8; i += stride) {
        float4 v0 = ((const float4*)src)[2 * i];
        float4 v1 = ((const float4*)src)[2 * i + 1];
        __half2 h0 = __floats2half2_rn(v0.x, v0.y);
        __half2 h1 = __floats2half2_rn(v0.z, v0.w);
        __half2 h2 = __floats2half2_rn(v1.x, v1.y);
        __half2 h3 = __floats2half2_rn(v1.z, v1.w);
        uint4 o = {*(uint32_t*)&h0, *(uint32_t*)&h1, *(uint32_t*)&h2, *(uint32_t*)&h3};
        ((uint4*)dst)[i] = o;
    }
}

// ---------------- router prep + router ----------------------------------------
__global__ void zero_counts_kernel() {
    if (threadIdx.x < NE) g_cnt[threadIdx.x] = 0;
}
__global__ void scan_kernel() {
    if (threadIdx.x == 0) {
        int s = 0;
        for (int e = 0; e < NE; e++) { g_off[e] = s; s += g_cnt[e]; }
    }
}
// rwT[e][h] = rw[h][e]  (8K elements)
__global__ __launch_bounds__(256) void transpose_rw_kernel(const float* __restrict__ rw) {
    int i = blockIdx.x * 256 + threadIdx.x;  // i over H*NE
    if (i < H_DIM * NE) {
        int h = i / NE, e = i % NE;
        g_rwT[e * H_DIM + h] = rw[i];
    }
}
__global__ __launch_bounds__(256) void router_kernel(const float* __restrict__ x,
                                                     const float* __restrict__ rb,
                                                     __half* __restrict__ xh) {
    int warp = threadIdx.x >> 5, lane = threadIdx.x & 31;
    int t = blockIdx.x * 8 + warp;
    if (t >= T_TOK) return;
    const float4* x4 = (const float4*)(x + (size_t)t * H_DIM);
    uint2* xo = (uint2*)(xh + (size_t)t * H_DIM);       // 4 halfs per slot
    const float4* rwT4 = (const float4*)g_rwT;
    float acc[NE];
#pragma unroll
    for (int e = 0; e < NE; e++) acc[e] = 0.f;
    for (int i = lane; i < H_DIM / 4; i += 32) {
        float4 xv = x4[i];
        __half2 h0 = __floats2half2_rn(xv.x, xv.y);
        __half2 h1 = __floats2half2_rn(xv.z, xv.w);
        uint2 o = {*(uint32_t*)&h0, *(uint32_t*)&h1};
        xo[i] = o;
#pragma unroll
        for (int e = 0; e < NE; e++) {
            float4 wv = rwT4[e * (H_DIM / 4) + i];
            acc[e] += xv.x * wv.x + xv.y * wv.y + xv.z * wv.z + xv.w * wv.w;
        }
    }
#pragma unroll
    for (int off = 16; off > 0; off >>= 1)
#pragma unroll
        for (int e = 0; e < NE; e++) acc[e] += __shfl_xor_sync(0xffffffffu, acc[e], off);
    if (lane == 0) {
#pragma unroll
        for (int e = 0; e < NE; e++) acc[e] += rb[e];
        int i1 = 0;
#pragma unroll
        for (int e = 1; e < NE; e++) if (acc[e] > acc[i1]) i1 = e;
        int i2 = -1;
#pragma unroll
        for (int e = 0; e < NE; e++) {
            if (e == i1) continue;
            if (i2 < 0 || acc[e] > acc[i2]) i2 = e;
        }
        float d   = acc[i2] - acc[i1];
        float w1p = 1.f / (1.f + expf(d));
        float w2p = 1.f - w1p;
        int p1 = atomicAdd(&g_cnt[i1], 1);
        g_tok[i1 * T_TOK + p1] = t;
        g_pE[2 * t] = i1; g_pP[2 * t] = p1; g_pW[2 * t] = w1p;
        int p2 = atomicAdd(&g_cnt[i2], 1);
        g_tok[i2 * T_TOK + p2] = t;
        g_pE[2 * t + 1] = i2; g_pP[2 * t + 1] = p2; g_pW[2 * t + 1] = w2p;
    }
}

// ---------------- fp16 mma.sync GEMM, BK=64, cp.async ring -------------------
#define A_STRIDE_B 144
#define B_STRIDE_B 272
#define A_BYTES   (BM * A_STRIDE_B)                 // 18432
#define B_BYTES   (BK * B_STRIDE_B)                 // 17408
#define STG_BYTES (A_BYTES + B_BYTES)               // 35840
#define SMEM_DYN  (DEPTH * STG_BYTES)               // 107520

template <bool PHASE2>
__global__ __launch_bounds__(256, 2) void moe_mma(const __half* __restrict__ X,
                                                  const __half* __restrict__ W,
                                                  const float* __restrict__ Bias) {
    constexpr int KDIM   = PHASE2 ? F_DIM : H_DIM;
    constexpr int NDIM   = PHASE2 ? H_DIM : F_DIM;
    constexpr int STAGES = KDIM / BK;               // 16 / 64

    const int e    = blockIdx.z;
    const int cnt  = g_cnt[e];
    const int row0 = blockIdx.y * BM;
    if (row0 >= cnt) return;
    const int col0 = blockIdx.x * BN;
    const int off  = g_off[e];
    const __half* Wexp = W + (size_t)e * KDIM * NDIM;

    extern __shared__ uint32_t smu[];
    __shared__ int toks_s[BM];
    const int tid = threadIdx.x;
    if (!PHASE2 && tid < BM) {
        int pos = row0 + tid;
        toks_s[tid] = (pos < cnt) ? g_tok[e * T_TOK + pos] : -1;
    }
    __syncthreads();

    // A loader: row = tid&127, half-of-row = tid>>7 -> 4x16B each (16KB/stage)
    const int arow = tid & 127, ah = tid >> 7;
    const __half* aptr;
    bool avalid = true;
    if (PHASE2) {
        aptr = g_h + (size_t)(off + row0 + arow) * F_DIM;
    } else {
        int tk = toks_s[arow];
        avalid = tk >= 0;
        aptr = avalid ? (X + (size_t)tk * H_DIM) : X;
    }
    // B loader: rows bk0+16i (i=0..3), chunk bc of 16 -> 4x16B each (16KB/stage)
    const int bk0 = tid >> 4, bc = tid & 15;
    const __half* bbase = Wexp + (size_t)bk0 * NDIM + col0 + bc * 8;

    const uint32_t smem_base = smem_u32(smu);
    const uint32_t a_off = (uint32_t)(arow * A_STRIDE_B + ah * 64);
    const uint32_t b_off = (uint32_t)(A_BYTES + bk0 * B_STRIDE_B + bc * 16);

    const int lane = tid & 31;
    const int g  = lane >> 2, t4 = lane & 3;
    const int wm = (tid >> 5) >> 2, wn = (tid >> 5) & 3;

    uint32_t a_frag_off[4];
#pragma unroll
    for (int mt = 0; mt < 4; mt++)
        a_frag_off[mt] = (uint32_t)((wm * 64 + mt * 16 + (lane & 15)) * A_STRIDE_B +
                                    (lane >> 4) * 16);
    uint32_t b_frag_off[2];
#pragma unroll
    for (int ntp = 0; ntp < 2; ntp++)
        b_frag_off[ntp] = (uint32_t)(A_BYTES +
            ((lane & 7) + ((lane >> 3) & 1) * 8) * B_STRIDE_B +
            wn * 64 + ntp * 32 + (lane >> 4) * 16);

    float acc[4][4][4];
#pragma unroll
    for (int mt = 0; mt < 4; mt++)
#pragma unroll
        for (int nt = 0; nt < 4; nt++)
#pragma unroll
            for (int r = 0; r < 4; r++) acc[mt][nt][r] = 0.f;

    auto issue = [&](int t) {
        uint32_t sb = smem_base + (uint32_t)(t % DEPTH) * STG_BYTES;
        int k0 = t * BK;
#pragma unroll
        for (int j = 0; j < 4; j++)
            cp16(sb + a_off + (uint32_t)j * 16u, aptr + k0 + ah * 32 + j * 8, avalid);
#pragma unroll
        for (int i = 0; i < 4; i++)
            cp16(sb + b_off + (uint32_t)(i * 16 * B_STRIDE_B),
                 bbase + (size_t)(k0 + i * 16) * NDIM, true);
        cp_commit();
    };

#pragma unroll
    for (int t = 0; t < DEPTH - 1; t++) issue(t);

    for (int s = 0; s < STAGES; s++) {
        cp_wait<DEPTH - 2>();
        __syncthreads();
        if (s + DEPTH - 1 < STAGES) issue(s + DEPTH - 1);

        const uint32_t sslot = smem_base + (uint32_t)(s % DEPTH) * STG_BYTES;
#pragma unroll
        for (int ks = 0; ks < 4; ks++) {
            uint32_t af[4][4], bf[2][4];
#pragma unroll
            for (int mt = 0; mt < 4; mt++)
                ldm4(af[mt], sslot + a_frag_off[mt] + (uint32_t)ks * 32u);
#pragma unroll
            for (int ntp = 0; ntp < 2; ntp++)
                ldm4t(bf[ntp], sslot + b_frag_off[ntp] + (uint32_t)(ks * 16 * B_STRIDE_B));
#pragma unroll
            for (int mt = 0; mt < 4; mt++)
#pragma unroll
                for (int ntp = 0; ntp < 2; ntp++) {
                    mma16(acc[mt][2 * ntp],     af[mt], &bf[ntp][0]);
                    mma16(acc[mt][2 * ntp + 1], af[mt], &bf[ntp][2]);
                }
        }
    }

    // ---- epilogue
#pragma unroll
    for (int mt = 0; mt < 4; mt++) {
#pragma unroll
        for (int rr = 0; rr < 2; rr++) {
            int m   = wm * 64 + mt * 16 + g + rr * 8;
            int pos = row0 + m;
            if (pos >= cnt) continue;
#pragma unroll
            for (int nt = 0; nt < 4; nt++) {
                int n = col0 + wn * 32 + nt * 8 + 2 * t4;
                float v0 = acc[mt][nt][rr * 2 + 0] + Bias[e * NDIM + n];
                float v1 = acc[mt][nt][rr * 2 + 1] + Bias[e * NDIM + n + 1];
                if (!PHASE2) {
                    __half2 o = __floats2half2_rn(gelu_tanh(v0), gelu_tanh(v1));
                    *(uint32_t*)(g_h + (size_t)(off + pos) * F_DIM + n) =
                        *(uint32_t*)&o;
                } else {
                    float2 o = {v0, v1};
                    *(float2*)(g_h2 + (size_t)(off + pos) * H_DIM + n) = o;
                }
            }
        }
    }
}

// ---------------- combine: out[t] = w0*h2[slot0] + w1*h2[slot1] --------------
__global__ __launch_bounds__(256) void combine_kernel(float* __restrict__ out) {
    int t = blockIdx.x;
    int c = threadIdx.x * 4;
    int e0 = g_pE[2 * t],     e1 = g_pE[2 * t + 1];
    int s0 = g_off[e0] + g_pP[2 * t];
    int s1 = g_off[e1] + g_pP[2 * t + 1];
    float w0 = g_pW[2 * t], w1 = g_pW[2 * t + 1];
    float4 a = *(const float4*)(g_h2 + (size_t)s0 * H_DIM + c);
    float4 b = *(const float4*)(g_h2 + (size_t)s1 * H_DIM + c);
    float4 o;
    o.x = w0 * a.x + w1 * b.x;
    o.y = w0 * a.y + w1 * b.y;
    o.z = w0 * a.z + w1 * b.z;
    o.w = w0 * a.w + w1 * b.w;
    *(float4*)(out + (size_t)t * H_DIM + c) = o;
}

// ---------------- launch ------------------------------------------------------
extern "C" void kernel_launch(void* const* d_in, const int* in_sizes, int n_in,
                              void* d_out, int out_size) {
    const float* x  = (const float*)d_in[0];  // [B,S,H]
    const float* w1 = (const float*)d_in[1];  // [E,H,F]
    const float* b1 = (const float*)d_in[2];  // [E,F]
    const float* w2 = (const float*)d_in[3];  // [E,F,H]
    const float* b2 = (const float*)d_in[4];  // [E,H]
    const float* rw = (const float*)d_in[5];  // [H,E]
    const float* rb = (const float*)d_in[6];  // [E]
    float* out = (float*)d_out;

    cudaFuncSetAttribute(moe_mma<false>, cudaFuncAttributeMaxDynamicSharedMemorySize,
                         SMEM_DYN);
    cudaFuncSetAttribute(moe_mma<true>, cudaFuncAttributeMaxDynamicSharedMemorySize,
                         SMEM_DYN);

    static __half *p_w1h = nullptr, *p_w2h = nullptr, *p_xh = nullptr;
    static cudaStream_t s2;
    static cudaEvent_t evStart, ev1, ev2;
    if (!p_w1h) {
        cudaGetSymbolAddress((void**)&p_w1h, g_w1h);
        cudaGetSymbolAddress((void**)&p_w2h, g_w2h);
        cudaGetSymbolAddress((void**)&p_xh, g_xh);
        cudaStreamCreateWithFlags(&s2, cudaStreamNonBlocking);
        cudaEventCreateWithFlags(&evStart, cudaEventDisableTiming);
        cudaEventCreateWithFlags(&ev1, cudaEventDisableTiming);
        cudaEventCreateWithFlags(&ev2, cudaEventDisableTiming);
    }

    dim3 block(256);
    dim3 grid1(F_DIM / BN, T_TOK / BM, NE);  // 32 x 64 x 8
    dim3 grid2(H_DIM / BN, T_TOK / BM, NE);  //  8 x 64 x 8

    // fork: weight converts on s2, overlapped with router (w1) and moe1 (w2)
    cudaEventRecord(evStart, 0);
    cudaStreamWaitEvent(s2, evStart, 0);
    to_half_kernel<<<4096, 256, 0, s2>>>(w1, p_w1h, (size_t)NE * H_DIM * F_DIM / 8);
    cudaEventRecord(ev1, s2);
    to_half_kernel<<<4096, 256, 0, s2>>>(w2, p_w2h, (size_t)NE * F_DIM * H_DIM / 8);
    cudaEventRecord(ev2, s2);

    transpose_rw_kernel<<<(H_DIM * NE + 255) / 256, 256>>>(rw);
    zero_counts_kernel<<<1, 32>>>();
    router_kernel<<<T_TOK / 8, 256>>>(x, rb, p_xh);
    scan_kernel<<<1, 32>>>();

    cudaStreamWaitEvent(0, ev1, 0);
    moe_mma<false><<<grid1, block, SMEM_DYN>>>(p_xh, p_w1h, b1);
    cudaStreamWaitEvent(0, ev2, 0);
    moe_mma<true ><<<grid2, block, SMEM_DYN>>>(nullptr, p_w2h, b2);
    combine_kernel<<<T_TOK, 256>>>(out);
}

// round 16
// speedup vs baseline: 1.0853x; 1.0119x over previous
#include <cuda_runtime.h>
#include <cuda_fp16.h>
#include <math.h>
#include <stdint.h>

#define T_TOK 8192
#define H_DIM 1024
#define F_DIM 4096
#define NE    8
#define BM    128
#define BN    128
#define BK    64
#define DEPTH 3

// ---------------- device scratch (static, no runtime allocation) ------------
__device__ __half g_h  [(size_t)(2 * T_TOK + BM) * F_DIM];  // gelu(x@w1+b1) fp16
__device__ __half g_h2 [(size_t)(2 * T_TOK + BM) * H_DIM];  // (h@w2+b2) fp16
__device__ __half g_w1h[(size_t)NE * H_DIM * F_DIM];        // fp16 w1
__device__ __half g_w2h[(size_t)NE * F_DIM * H_DIM];        // fp16 w2
__device__ __half g_xh [(size_t)T_TOK * H_DIM];             // fp16 x
__device__ float  g_rwT[NE * H_DIM];                        // transposed router w
__device__ int    g_tok[NE * T_TOK];
__device__ int    g_cnt[NE];
__device__ int    g_off[NE];
__device__ int    g_done;                                   // router last-block flag
__device__ int    g_pE[2 * T_TOK];
__device__ int    g_pP[2 * T_TOK];
__device__ float  g_pW[2 * T_TOK];

// ---------------- helpers ----------------------------------------------------
__device__ __forceinline__ void mma16(float* d, const uint32_t* a, const uint32_t* b) {
    asm volatile(
        "mma.sync.aligned.m16n8k16.row.col.f32.f16.f16.f32 "
        "{%0,%1,%2,%3}, {%4,%5,%6,%7}, {%8,%9}, {%0,%1,%2,%3};"
        : "+f"(d[0]), "+f"(d[1]), "+f"(d[2]), "+f"(d[3])
        : "r"(a[0]), "r"(a[1]), "r"(a[2]), "r"(a[3]), "r"(b[0]), "r"(b[1]));
}
__device__ __forceinline__ void ldm4(uint32_t* r, uint32_t addr) {
    asm volatile("ldmatrix.sync.aligned.m8n8.x4.shared.b16 {%0,%1,%2,%3}, [%4];"
                 : "=r"(r[0]), "=r"(r[1]), "=r"(r[2]), "=r"(r[3]) : "r"(addr));
}
__device__ __forceinline__ void ldm4t(uint32_t* r, uint32_t addr) {
    asm volatile("ldmatrix.sync.aligned.m8n8.x4.trans.shared.b16 {%0,%1,%2,%3}, [%4];"
                 : "=r"(r[0]), "=r"(r[1]), "=r"(r[2]), "=r"(r[3]) : "r"(addr));
}
__device__ __forceinline__ uint32_t smem_u32(const void* p) {
    uint32_t a;
    asm("{ .reg .u64 t; cvta.to.shared.u64 t, %1; cvt.u32.u64 %0, t; }" : "=r"(a) : "l"(p));
    return a;
}
__device__ __forceinline__ void cp16(uint32_t dst, const void* src, bool pred) {
    int sz = pred ? 16 : 0;
    asm volatile("cp.async.cg.shared.global [%0], [%1], 16, %2;"
                 :: "r"(dst), "l"(src), "r"(sz) : "memory");
}
__device__ __forceinline__ void cp_commit() {
    asm volatile("cp.async.commit_group;" ::: "memory");
}
template <int N>
__device__ __forceinline__ void cp_wait() {
    asm volatile("cp.async.wait_group %0;" :: "n"(N) : "memory");
}
__device__ __forceinline__ float gelu_tanh(float v) {
    float u = 0.7978845608028654f * (v + 0.044715f * v * v * v);
    return 0.5f * v * (1.0f + tanhf(u));
}

// ---------------- fp32 -> fp16 convert pass ----------------------------------
__global__ __launch_bounds__(256) void to_half_kernel(const float* __restrict__ src,
                                                      __half* __restrict__ dst,
                                                      size_t n8) {
    size_t stride = (size_t)gridDim.x * blockDim.x;
    for (size_t i = blockIdx.x * (size_t)blockDim.x + threadIdx.x; i < n8; i += stride) {
        float4 v0 = ((const float4*)src)[2 * i];
        float4 v1 = ((const float4*)src)[2 * i + 1];
        __half2 h0 = __floats2half2_rn(v0.x, v0.y);
        __half2 h1 = __floats2half2_rn(v0.z, v0.w);
        __half2 h2 = __floats2half2_rn(v1.x, v1.y);
        __half2 h3 = __floats2half2_rn(v1.z, v1.w);
        uint4 o = {*(uint32_t*)&h0, *(uint32_t*)&h1, *(uint32_t*)&h2, *(uint32_t*)&h3};
        ((uint4*)dst)[i] = o;
    }
}

// ---------------- router prep + router ----------------------------------------
// rwT[e][h] = rw[h][e]; also zero counts + done-flag (fused, one launch)
__global__ __launch_bounds__(256) void prep_kernel(const float* __restrict__ rw) {
    int i = blockIdx.x * 256 + threadIdx.x;  // i over H*NE
    if (i < H_DIM * NE) {
        int h = i / NE, e = i % NE;
        g_rwT[e * H_DIM + h] = rw[i];
    }
    if (i < NE) g_cnt[i] = 0;
    if (i == 0) g_done = 0;
}
// router: logits via coalesced rwT, fp16 x emission, top-2; last block scans.
__global__ __launch_bounds__(256) void router_kernel(const float* __restrict__ x,
                                                     const float* __restrict__ rb,
                                                     __half* __restrict__ xh) {
    int warp = threadIdx.x >> 5, lane = threadIdx.x & 31;
    int t = blockIdx.x * 8 + warp;
    if (t < T_TOK) {
        const float4* x4 = (const float4*)(x + (size_t)t * H_DIM);
        uint2* xo = (uint2*)(xh + (size_t)t * H_DIM);
        const float4* rwT4 = (const float4*)g_rwT;
        float acc[NE];
#pragma unroll
        for (int e = 0; e < NE; e++) acc[e] = 0.f;
        for (int i = lane; i < H_DIM / 4; i += 32) {
            float4 xv = x4[i];
            __half2 h0 = __floats2half2_rn(xv.x, xv.y);
            __half2 h1 = __floats2half2_rn(xv.z, xv.w);
            uint2 o = {*(uint32_t*)&h0, *(uint32_t*)&h1};
            xo[i] = o;
#pragma unroll
            for (int e = 0; e < NE; e++) {
                float4 wv = rwT4[e * (H_DIM / 4) + i];
                acc[e] += xv.x * wv.x + xv.y * wv.y + xv.z * wv.z + xv.w * wv.w;
            }
        }
#pragma unroll
        for (int off = 16; off > 0; off >>= 1)
#pragma unroll
            for (int e = 0; e < NE; e++)
                acc[e] += __shfl_xor_sync(0xffffffffu, acc[e], off);
        if (lane == 0) {
#pragma unroll
            for (int e = 0; e < NE; e++) acc[e] += rb[e];
            int i1 = 0;
#pragma unroll
            for (int e = 1; e < NE; e++) if (acc[e] > acc[i1]) i1 = e;
            int i2 = -1;
#pragma unroll
            for (int e = 0; e < NE; e++) {
                if (e == i1) continue;
                if (i2 < 0 || acc[e] > acc[i2]) i2 = e;
            }
            float d   = acc[i2] - acc[i1];
            float w1p = 1.f / (1.f + expf(d));
            float w2p = 1.f - w1p;
            int p1 = atomicAdd(&g_cnt[i1], 1);
            g_tok[i1 * T_TOK + p1] = t;
            g_pE[2 * t] = i1; g_pP[2 * t] = p1; g_pW[2 * t] = w1p;
            int p2 = atomicAdd(&g_cnt[i2], 1);
            g_tok[i2 * T_TOK + p2] = t;
            g_pE[2 * t + 1] = i2; g_pP[2 * t + 1] = p2; g_pW[2 * t + 1] = w2p;
        }
    }
    // last finished block computes the offsets (fused scan)
    __syncthreads();
    if (threadIdx.x == 0) {
        __threadfence();
        if (atomicAdd(&g_done, 1) == gridDim.x - 1) {
            int s = 0;
#pragma unroll
            for (int e = 0; e < NE; e++) { g_off[e] = s; s += g_cnt[e]; }
        }
    }
}

// ---------------- fp16 mma.sync GEMM, BK=64, cp.async ring -------------------
#define A_STRIDE_B 144
#define B_STRIDE_B 272
#define A_BYTES   (BM * A_STRIDE_B)                 // 18432
#define B_BYTES   (BK * B_STRIDE_B)                 // 17408
#define STG_BYTES (A_BYTES + B_BYTES)               // 35840
#define SMEM_DYN  (DEPTH * STG_BYTES)               // 107520

template <bool PHASE2>
__global__ __launch_bounds__(256, 2) void moe_mma(const __half* __restrict__ X,
                                                  const __half* __restrict__ W,
                                                  const float* __restrict__ Bias) {
    constexpr int KDIM   = PHASE2 ? F_DIM : H_DIM;
    constexpr int NDIM   = PHASE2 ? H_DIM : F_DIM;
    constexpr int STAGES = KDIM / BK;               // 16 / 64

    const int e    = blockIdx.z;
    const int cnt  = g_cnt[e];
    const int row0 = blockIdx.y * BM;
    if (row0 >= cnt) return;
    const int col0 = blockIdx.x * BN;
    const int off  = g_off[e];
    const __half* Wexp = W + (size_t)e * KDIM * NDIM;

    extern __shared__ uint32_t smu[];
    __shared__ int toks_s[BM];
    const int tid = threadIdx.x;
    if (!PHASE2 && tid < BM) {
        int pos = row0 + tid;
        toks_s[tid] = (pos < cnt) ? g_tok[e * T_TOK + pos] : -1;
    }
    __syncthreads();

    // A loader: row = tid&127, half-of-row = tid>>7 -> 4x16B each (16KB/stage)
    const int arow = tid & 127, ah = tid >> 7;
    const __half* aptr;
    bool avalid = true;
    if (PHASE2) {
        aptr = g_h + (size_t)(off + row0 + arow) * F_DIM;
    } else {
        int tk = toks_s[arow];
        avalid = tk >= 0;
        aptr = avalid ? (X + (size_t)tk * H_DIM) : X;
    }
    // B loader: rows bk0+16i (i=0..3), chunk bc of 16 -> 4x16B each (16KB/stage)
    const int bk0 = tid >> 4, bc = tid & 15;
    const __half* bbase = Wexp + (size_t)bk0 * NDIM + col0 + bc * 8;

    const uint32_t smem_base = smem_u32(smu);
    const uint32_t a_off = (uint32_t)(arow * A_STRIDE_B + ah * 64);
    const uint32_t b_off = (uint32_t)(A_BYTES + bk0 * B_STRIDE_B + bc * 16);

    const int lane = tid & 31;
    const int g  = lane >> 2, t4 = lane & 3;
    const int wm = (tid >> 5) >> 2, wn = (tid >> 5) & 3;

    uint32_t a_frag_off[4];
#pragma unroll
    for (int mt = 0; mt < 4; mt++)
        a_frag_off[mt] = (uint32_t)((wm * 64 + mt * 16 + (lane & 15)) * A_STRIDE_B +
                                    (lane >> 4) * 16);
    uint32_t b_frag_off[2];
#pragma unroll
    for (int ntp = 0; ntp < 2; ntp++)
        b_frag_off[ntp] = (uint32_t)(A_BYTES +
            ((lane & 7) + ((lane >> 3) & 1) * 8) * B_STRIDE_B +
            wn * 64 + ntp * 32 + (lane >> 4) * 16);

    float acc[4][4][4];
#pragma unroll
    for (int mt = 0; mt < 4; mt++)
#pragma unroll
        for (int nt = 0; nt < 4; nt++)
#pragma unroll
            for (int r = 0; r < 4; r++) acc[mt][nt][r] = 0.f;

    auto issue = [&](int t) {
        uint32_t sb = smem_base + (uint32_t)(t % DEPTH) * STG_BYTES;
        int k0 = t * BK;
#pragma unroll
        for (int j = 0; j < 4; j++)
            cp16(sb + a_off + (uint32_t)j * 16u, aptr + k0 + ah * 32 + j * 8, avalid);
#pragma unroll
        for (int i = 0; i < 4; i++)
            cp16(sb + b_off + (uint32_t)(i * 16 * B_STRIDE_B),
                 bbase + (size_t)(k0 + i * 16) * NDIM, true);
        cp_commit();
    };

#pragma unroll
    for (int t = 0; t < DEPTH - 1; t++) issue(t);

    for (int s = 0; s < STAGES; s++) {
        cp_wait<DEPTH - 2>();
        __syncthreads();
        if (s + DEPTH - 1 < STAGES) issue(s + DEPTH - 1);

        const uint32_t sslot = smem_base + (uint32_t)(s % DEPTH) * STG_BYTES;
#pragma unroll
        for (int ks = 0; ks < 4; ks++) {
            uint32_t af[4][4], bf[2][4];
#pragma unroll
            for (int mt = 0; mt < 4; mt++)
                ldm4(af[mt], sslot + a_frag_off[mt] + (uint32_t)ks * 32u);
#pragma unroll
            for (int ntp = 0; ntp < 2; ntp++)
                ldm4t(bf[ntp], sslot + b_frag_off[ntp] + (uint32_t)(ks * 16 * B_STRIDE_B));
#pragma unroll
            for (int mt = 0; mt < 4; mt++)
#pragma unroll
                for (int ntp = 0; ntp < 2; ntp++) {
                    mma16(acc[mt][2 * ntp],     af[mt], &bf[ntp][0]);
                    mma16(acc[mt][2 * ntp + 1], af[mt], &bf[ntp][2]);
                }
        }
    }

    // ---- epilogue
#pragma unroll
    for (int mt = 0; mt < 4; mt++) {
#pragma unroll
        for (int rr = 0; rr < 2; rr++) {
            int m   = wm * 64 + mt * 16 + g + rr * 8;
            int pos = row0 + m;
            if (pos >= cnt) continue;
#pragma unroll
            for (int nt = 0; nt < 4; nt++) {
                int n = col0 + wn * 32 + nt * 8 + 2 * t4;
                float v0 = acc[mt][nt][rr * 2 + 0] + Bias[e * NDIM + n];
                float v1 = acc[mt][nt][rr * 2 + 1] + Bias[e * NDIM + n + 1];
                if (!PHASE2) {
                    __half2 o = __floats2half2_rn(gelu_tanh(v0), gelu_tanh(v1));
                    *(uint32_t*)(g_h + (size_t)(off + pos) * F_DIM + n) =
                        *(uint32_t*)&o;
                } else {
                    __half2 o = __floats2half2_rn(v0, v1);
                    *(uint32_t*)(g_h2 + (size_t)(off + pos) * H_DIM + n) =
                        *(uint32_t*)&o;
                }
            }
        }
    }
}

// ---------------- combine: out[t] = w0*h2[slot0] + w1*h2[slot1] --------------
__global__ __launch_bounds__(256) void combine_kernel(float* __restrict__ out) {
    int t = blockIdx.x;
    int c = threadIdx.x * 4;
    int e0 = g_pE[2 * t],     e1 = g_pE[2 * t + 1];
    int s0 = g_off[e0] + g_pP[2 * t];
    int s1 = g_off[e1] + g_pP[2 * t + 1];
    float w0 = g_pW[2 * t], w1 = g_pW[2 * t + 1];
    uint2 ar = *(const uint2*)(g_h2 + (size_t)s0 * H_DIM + c);
    uint2 br = *(const uint2*)(g_h2 + (size_t)s1 * H_DIM + c);
    float2 a0 = __half22float2(*(__half2*)&ar.x);
    float2 a1 = __half22float2(*(__half2*)&ar.y);
    float2 b0 = __half22float2(*(__half2*)&br.x);
    float2 b1 = __half22float2(*(__half2*)&br.y);
    float4 o;
    o.x = w0 * a0.x + w1 * b0.x;
    o.y = w0 * a0.y + w1 * b0.y;
    o.z = w0 * a1.x + w1 * b1.x;
    o.w = w0 * a1.y + w1 * b1.y;
    *(float4*)(out + (size_t)t * H_DIM + c) = o;
}

// ---------------- launch ------------------------------------------------------
extern "C" void kernel_launch(void* const* d_in, const int* in_sizes, int n_in,
                              void* d_out, int out_size) {
    const float* x  = (const float*)d_in[0];  // [B,S,H]
    const float* w1 = (const float*)d_in[1];  // [E,H,F]
    const float* b1 = (const float*)d_in[2];  // [E,F]
    const float* w2 = (const float*)d_in[3];  // [E,F,H]
    const float* b2 = (const float*)d_in[4];  // [E,H]
    const float* rw = (const float*)d_in[5];  // [H,E]
    const float* rb = (const float*)d_in[6];  // [E]
    float* out = (float*)d_out;

    cudaFuncSetAttribute(moe_mma<false>, cudaFuncAttributeMaxDynamicSharedMemorySize,
                         SMEM_DYN);
    cudaFuncSetAttribute(moe_mma<true>, cudaFuncAttributeMaxDynamicSharedMemorySize,
                         SMEM_DYN);

    static __half *p_w1h = nullptr, *p_w2h = nullptr, *p_xh = nullptr;
    static cudaStream_t s2;
    static cudaEvent_t evStart, ev1, ev2;
    if (!p_w1h) {
        cudaGetSymbolAddress((void**)&p_w1h, g_w1h);
        cudaGetSymbolAddress((void**)&p_w2h, g_w2h);
        cudaGetSymbolAddress((void**)&p_xh, g_xh);
        cudaStreamCreateWithFlags(&s2, cudaStreamNonBlocking);
        cudaEventCreateWithFlags(&evStart, cudaEventDisableTiming);
        cudaEventCreateWithFlags(&ev1, cudaEventDisableTiming);
        cudaEventCreateWithFlags(&ev2, cudaEventDisableTiming);
    }

    dim3 block(256);
    dim3 grid1(F_DIM / BN, T_TOK / BM, NE);  // 32 x 64 x 8
    dim3 grid2(H_DIM / BN, T_TOK / BM, NE);  //  8 x 64 x 8

    // fork: weight converts on s2, overlapped with router (w1) and moe1 (w2)
    cudaEventRecord(evStart, 0);
    cudaStreamWaitEvent(s2, evStart, 0);
    to_half_kernel<<<4096, 256, 0, s2>>>(w1, p_w1h, (size_t)NE * H_DIM * F_DIM / 8);
    cudaEventRecord(ev1, s2);
    to_half_kernel<<<4096, 256, 0, s2>>>(w2, p_w2h, (size_t)NE * F_DIM * H_DIM / 8);
    cudaEventRecord(ev2, s2);

    prep_kernel<<<(H_DIM * NE + 255) / 256, 256>>>(rw);
    router_kernel<<<T_TOK / 8, 256>>>(x, rb, p_xh);   // includes fused scan

    cudaStreamWaitEvent(0, ev1, 0);
    moe_mma<false><<<grid1, block, SMEM_DYN>>>(p_xh, p_w1h, b1);
    cudaStreamWaitEvent(0, ev2, 0);
    moe_mma<true ><<<grid2, block, SMEM_DYN>>>(nullptr, p_w2h, b2);
    combine_kernel<<<T_TOK, 256>>>(out);
}